// round 2
// baseline (speedup 1.0000x reference)
#include <cuda_runtime.h>
#include <cuda_bf16.h>
#include <cstdint>
#include <math.h>

#define FULLMASK 0xffffffffu
#define NENT   8192
#define EMB    256
#define KDIM   32
#define ARDIM  1024
#define UTYPE  233
#define CL     8
#define TPB    1024

// ---- smem layout (float offsets) ----
#define OFF_KEYS   0        // 32*1024
#define OFF_MASK   32768    // 8192 (CTA0 only uses)
#define OFF_W3T    40960    // 4096 = [32][128] transposed W_a3 slice
#define OFF_PART   45056    // 2048 = 8 CTAs x 256 rows (CTA0 mailbox)
#define OFF_ARS    47104    // 128  (this CTA's ar slice)
#define OFF_C0     47232    // 256  (b_a0 + func_embed)
#define OFF_A      47488    // 256  relu(i0)
#define OFF_X      47744    // 64
#define OFF_Q      47808    // 32
#define OFF_H      47840    // 32
#define OFF_QN     47872    // 32
#define OFF_QNL    47904    // 32  local qn copy
#define OFF_G      47936    // 128 (4 gates x 32)
#define OFF_CENT   48064    // 32  (CTA0 master)
#define OFF_CENTL  48096    // 32  local copy
#define OFF_MB     48128    // 24: sums[8], maxv[8], maxi[8]
#define OFF_BC     48152    // 4 : rowinv, pick, pending, pad (CTA0 master)
#define OFF_BCL    48156    // 4 : local copy
#define OFF_FLAGS  48160    // 1 : done
#define OFF_RED    48164    // 96: 32 warps x (sum, maxv, maxi)
#define SMEM_FLOATS 48260
#define SMEM_BYTES (SMEM_FLOATS * 4)

static __device__ float g_keys[KDIM * NENT];   // k-major: g_keys[k*NENT + e]

// ---------------- helpers ----------------
__device__ __forceinline__ uint32_t smem_u32(const void* p) {
    return (uint32_t)__cvta_generic_to_shared(p);
}
__device__ __forceinline__ uint32_t mapa_rank(uint32_t addr, uint32_t rank) {
    uint32_t r;
    asm volatile("mapa.shared::cluster.u32 %0, %1, %2;" : "=r"(r) : "r"(addr), "r"(rank));
    return r;
}
__device__ __forceinline__ float ld_remote_f32(uint32_t addr) {
    float v;
    asm volatile("ld.shared::cluster.f32 %0, [%1];" : "=f"(v) : "r"(addr));
    return v;
}
__device__ __forceinline__ void st_remote_f32(uint32_t addr, float v) {
    asm volatile("st.shared::cluster.f32 [%0], %1;" :: "r"(addr), "f"(v));
}
__device__ __forceinline__ void cluster_sync_all() {
    asm volatile("barrier.cluster.arrive.aligned;" ::: "memory");
    asm volatile("barrier.cluster.wait.aligned;" ::: "memory");
}
__device__ __forceinline__ uint32_t ctarank() {
    uint32_t r;
    asm("mov.u32 %0, %%cluster_ctarank;" : "=r"(r));
    return r;
}
__device__ __forceinline__ float wsum(float x) {
#pragma unroll
    for (int o = 16; o > 0; o >>= 1) x += __shfl_xor_sync(FULLMASK, x, o);
    return x;
}
__device__ __forceinline__ void argmax_red(float& v, float& idx) {
#pragma unroll
    for (int o = 16; o > 0; o >>= 1) {
        float ov = __shfl_xor_sync(FULLMASK, v, o);
        float oi = __shfl_xor_sync(FULLMASK, idx, o);
        if (ov > v || (ov == v && oi < idx)) { v = ov; idx = oi; }
    }
}
__device__ __forceinline__ float sigmoidf_(float x) { return 1.f / (1.f + expf(-x)); }
// layernorm over 32 lanes (lane = component)
__device__ __forceinline__ float lnf(float x, float g, float b) {
    float m = wsum(x) * (1.f / 32.f);
    float d = x - m;
    float var = wsum(d * d) * (1.f / 32.f);
    return d * rsqrtf(var + 1e-5f) * g + b;
}

// ---------------- keys: g_keys[k][e] = W_k[k,:]·enc[e,:] + b_k[k] ----------------
__global__ void __launch_bounds__(256) keys_kernel(const float4* __restrict__ Wk,
                                                   const float* __restrict__ bk,
                                                   const float4* __restrict__ enc) {
    int g = blockIdx.x * blockDim.x + threadIdx.x;
    int e = g >> 5;
    int lane = g & 31;
    if (e >= NENT) return;
    const float4* er = enc + (size_t)e * 64;
    const float4* wr = Wk + (size_t)lane * 64;
    float acc = 0.f;
#pragma unroll 8
    for (int j = 0; j < 64; j++) {
        float4 a = er[j];
        float4 b = wr[j];
        acc += a.x * b.x + a.y * b.y + a.z * b.z + a.w * b.w;
    }
    g_keys[lane * NENT + e] = acc + bk[lane];
}

// ---------------- persistent sequential cluster kernel ----------------
__global__ void __cluster_dims__(CL, 1, 1) __launch_bounds__(TPB, 1)
seq_kernel(float* __restrict__ out,
           const int* __restrict__ p_steps,
           const float* __restrict__ entity_mask,
           const float* __restrict__ ar_in,
           const float* __restrict__ utype,
           const float* __restrict__ W_fe, const float* __restrict__ b_fe,
           const float* __restrict__ W_a0, const float* __restrict__ b_a0,
           const float* __restrict__ W_a1, const float* __restrict__ b_a1,
           const float* __restrict__ W_f,  const float* __restrict__ b_f,
           const float* __restrict__ W_i0, const float* __restrict__ b_i0,
           const float* __restrict__ W_i1, const float* __restrict__ b_i1,
           const float* __restrict__ W_o,  const float* __restrict__ b_o,
           const float* __restrict__ ln_g, const float* __restrict__ ln_b,
           const float* __restrict__ W_a3, const float* __restrict__ b_a3)
{
    extern __shared__ float sm[];
    const int tid  = threadIdx.x;
    const int lane = tid & 31;
    const int wid  = tid >> 5;
    const uint32_t rank = ctarank();
    const uint32_t smbase = smem_u32(sm);

    // steps (robust to int32 or f32 encoding)
    int raw = p_steps[0];
    int stepsv = (raw >= 0 && raw <= 100000) ? raw : (int)__int_as_float(raw);
    int steps = stepsv < 64 ? stepsv : 64;
    if (steps < 0) steps = 0;

    // ---- prologue ----
#pragma unroll
    for (int k = 0; k < 32; k++)
        sm[OFF_KEYS + k * 1024 + tid] = g_keys[k * NENT + (int)rank * 1024 + tid];
#pragma unroll
    for (int i = 0; i < 8; i++)
        sm[OFF_MASK + i * 1024 + tid] = entity_mask[i * 1024 + tid];
#pragma unroll
    for (int i = 0; i < 4; i++) {
        int idx = tid + i * 1024;                     // idx = k*128 + t
        sm[OFF_W3T + idx] = W_a3[((int)rank * 128 + (idx & 127)) * 32 + (idx >> 7)];
    }
    float ba3 = 0.f;
    if (tid < 128) {
        sm[OFF_ARS + tid] = ar_in[(int)rank * 128 + tid];
        ba3 = b_a3[(int)rank * 128 + tid];
    }
    if (rank == 0 && tid < 32) { sm[OFF_Q + tid] = 0.f; sm[OFF_H + tid] = 0.f; sm[OFF_QN + tid] = 0.f; }
    if (tid == 0) { sm[OFF_FLAGS] = 0.f; sm[OFF_BCL + 2] = 0.f; }
    if (rank == 0) {  // c0 = b_a0 + relu(W_fe@utype + b_fe); warp wid does rows wid*8..+7
        for (int rr = 0; rr < 8; rr++) {
            int row = wid * 8 + rr;
            float acc = 0.f;
#pragma unroll
            for (int i = 0; i < 8; i++) {
                int j = lane + (i << 5);
                if (j < UTYPE) acc += W_fe[row * UTYPE + j] * utype[j];
            }
            acc = wsum(acc);
            if (lane == 0) sm[OFF_C0 + row] = b_a0[row] + fmaxf(0.f, acc + b_fe[row]);
        }
    }
    cluster_sync_all();

    // ---- sequential steps ----
    for (int step = 0; step < steps; ++step) {
        // S0: K-split GEMV partials: this CTA covers ar cols [rank*128, +128) for all 256 rows
        __syncthreads();   // ar_s updated in prior S4
#pragma unroll
        for (int it = 0; it < 8; it++) {
            int row = it * 32 + wid;
            const float* wrow = W_a0 + (size_t)row * ARDIM + (int)rank * 128;
            float acc = 0.f;
#pragma unroll
            for (int i = 0; i < 4; i++) acc += wrow[lane + (i << 5)] * sm[OFF_ARS + lane + (i << 5)];
            acc = wsum(acc);
            if (lane == 0)
                st_remote_f32(mapa_rank(smbase + (OFF_PART + (int)rank * 256 + row) * 4u, 0u), acc);
        }
        cluster_sync_all();   // A

        // S1: CTA0 — i0 sum, relu, i1, LSTM -> qn
        if (rank == 0) {
            bool active = (sm[OFF_FLAGS] == 0.f);
            if (tid < 256) {
                float s = 0.f;
#pragma unroll
                for (int r = 0; r < 8; r++) s += sm[OFF_PART + r * 256 + tid];
                sm[OFF_A + tid] = fmaxf(0.f, s + sm[OFF_C0 + tid]);
            }
            __syncthreads();
            {   // i1 row per warp
                const float* wrow = W_a1 + wid * EMB;
                float acc = 0.f;
#pragma unroll
                for (int i = 0; i < 8; i++) { int j = lane + (i << 5); acc += wrow[j] * sm[OFF_A + j]; }
                acc = wsum(acc);
                if (lane == 0) sm[OFF_X + wid] = fmaxf(0.f, acc + b_a1[wid]);
            }
            if (wid == 1) sm[OFF_X + 32 + lane] = sm[OFF_Q + lane];
            __syncthreads();
            {   // 4 gate pre-activations; warp = output row
                float xl = sm[OFF_X + lane], xh = sm[OFF_X + 32 + lane];
                float gf = W_f [wid * 64 + lane] * xl + W_f [wid * 64 + 32 + lane] * xh;
                float g0 = W_i0[wid * 64 + lane] * xl + W_i0[wid * 64 + 32 + lane] * xh;
                float g1 = W_i1[wid * 64 + lane] * xl + W_i1[wid * 64 + 32 + lane] * xh;
                float go = W_o [wid * 64 + lane] * xl + W_o [wid * 64 + 32 + lane] * xh;
                gf = wsum(gf); g0 = wsum(g0); g1 = wsum(g1); go = wsum(go);
                if (lane == 0) {
                    sm[OFF_G +      wid] = gf + b_f [wid];
                    sm[OFF_G + 32 + wid] = g0 + b_i0[wid];
                    sm[OFF_G + 64 + wid] = g1 + b_i1[wid];
                    sm[OFF_G + 96 + wid] = go + b_o [wid];
                }
            }
            __syncthreads();
            if (wid == 0) {
                float g = ln_g[lane], b = ln_b[lane];
                float gF = sm[OFF_G + lane], g0 = sm[OFF_G + 32 + lane];
                float g1 = sm[OFF_G + 64 + lane], gO = sm[OFF_G + 96 + lane];
                float forget = lnf(sigmoidf_(gF), g, b);
                float rem    = lnf(sigmoidf_(g0) * tanhf(g1), g, b);
                float hn     = rem + forget * sm[OFF_H + lane];
                float qn     = tanhf(hn) * lnf(sigmoidf_(gO), g, b);
                sm[OFF_QN + lane] = qn;
                if (active) { sm[OFF_Q + lane] = qn; sm[OFF_H + lane] = hn; }
            }
        }
        cluster_sync_all();   // B

        // S2: v per entity + CTA reductions
        if (wid == 0)
            sm[OFF_QNL + lane] = ld_remote_f32(mapa_rank(smbase + (OFF_QN + lane) * 4u, 0u));
        __syncthreads();
        float acc = 0.f;
#pragma unroll
        for (int k = 0; k < 32; k++) acc += sm[OFF_QNL + k] * sm[OFF_KEYS + k * 1024 + tid];
        float sig = 1.f / (1.f + expf(-acc));
        float v = expf(logf(sig) / 0.8f);
        {
            float s = wsum(v);
            float mv = v, mi = (float)((int)rank * 1024 + tid);
            argmax_red(mv, mi);
            if (lane == 0) {
                sm[OFF_RED + wid * 3 + 0] = s;
                sm[OFF_RED + wid * 3 + 1] = mv;
                sm[OFF_RED + wid * 3 + 2] = mi;
            }
        }
        __syncthreads();
        if (wid == 0) {
            float s2 = sm[OFF_RED + lane * 3 + 0];
            float m2 = sm[OFF_RED + lane * 3 + 1];
            float i2 = sm[OFF_RED + lane * 3 + 2];
            s2 = wsum(s2); argmax_red(m2, i2);
            if (lane == 0) {
                st_remote_f32(mapa_rank(smbase + (OFF_MB +      rank) * 4u, 0u), s2);
                st_remote_f32(mapa_rank(smbase + (OFF_MB +  8 + rank) * 4u, 0u), m2);
                st_remote_f32(mapa_rank(smbase + (OFF_MB + 16 + rank) * 4u, 0u), i2);
            }
        }
        cluster_sync_all();   // C

        // S3: CTA0 warp0 — global reduce, pick, selection, broadcast
        if (rank == 0 && wid == 0) {
            float s  = (lane < 8) ? sm[OFF_MB + lane]      : 0.f;
            float m  = (lane < 8) ? sm[OFF_MB + 8 + lane]  : -INFINITY;
            float ix = (lane < 8) ? sm[OFF_MB + 16 + lane] : 1e9f;
            float ssum = wsum(s);
            argmax_red(m, ix);
            int pick = (int)ix;
            bool active = (sm[OFF_FLAGS] == 0.f);
            bool valid  = (ssum != 0.f);
            float rowinv = (active && valid) ? 1.f / ssum : 0.f;
            float selv = g_keys[lane * NENT + pick];
            float mean = wsum(selv) * (1.f / 32.f);
            float cen = selv - mean;
            bool nanfree = (__ballot_sync(FULLMASK, isnan(cen)) == 0u);
            bool hit = active && valid && (sm[OFF_MASK + pick] != 0.f);
            bool pending = hit && nanfree;
            sm[OFF_CENT + lane] = cen;
            if (lane == 0) {
                sm[OFF_BC + 0] = rowinv;
                sm[OFF_BC + 1] = (float)pick;
                sm[OFF_BC + 2] = pending ? 1.f : 0.f;
                if (hit) { sm[OFF_MASK + pick] = 0.f; out[(size_t)NENT * NENT + pick] = 1.f; }
                if (hit && !nanfree) sm[OFF_FLAGS] = 1.f;
            }
        }
        cluster_sync_all();   // D

        // S4: broadcast copy, row write, local ar update
        if (wid == 0) {
            if (lane < 4)
                sm[OFF_BCL + lane] = ld_remote_f32(mapa_rank(smbase + (OFF_BC + lane) * 4u, 0u));
            sm[OFF_CENTL + lane] = ld_remote_f32(mapa_rank(smbase + (OFF_CENT + lane) * 4u, 0u));
        }
        __syncthreads();
        out[(size_t)step * NENT + (int)rank * 1024 + tid] = v * sm[OFF_BCL + 0];
        if (sm[OFF_BCL + 2] != 0.f && tid < 128) {
            float d = 0.f;
#pragma unroll
            for (int k = 0; k < 32; k++) d += sm[OFF_W3T + k * 128 + tid] * sm[OFF_CENTL + k];
            sm[OFF_ARS + tid] += fmaxf(0.f, d + ba3);
        }
    }

    // epilogue: ar_out
    __syncthreads();
    if (tid < 128)
        out[(size_t)NENT * NENT + NENT + (int)rank * 128 + tid] = sm[OFF_ARS + tid];
}

extern "C" void kernel_launch(void* const* d_in, const int* in_sizes, int n_in,
                              void* d_out, int out_size) {
    const float* utype   = (const float*)d_in[0];
    const float* emask   = (const float*)d_in[1];
    const float* enc     = (const float*)d_in[2];
    const float* ar      = (const float*)d_in[3];
    const float* W_fe    = (const float*)d_in[4];
    const float* b_fe    = (const float*)d_in[5];
    const float* W_k     = (const float*)d_in[6];
    const float* b_k     = (const float*)d_in[7];
    const float* W_a0    = (const float*)d_in[8];
    const float* b_a0    = (const float*)d_in[9];
    const float* W_a1    = (const float*)d_in[10];
    const float* b_a1    = (const float*)d_in[11];
    const float* W_f     = (const float*)d_in[12];
    const float* b_f     = (const float*)d_in[13];
    const float* W_i0    = (const float*)d_in[14];
    const float* b_i0    = (const float*)d_in[15];
    const float* W_i1    = (const float*)d_in[16];
    const float* b_i1    = (const float*)d_in[17];
    const float* W_o     = (const float*)d_in[18];
    const float* b_o     = (const float*)d_in[19];
    const float* ln_g    = (const float*)d_in[20];
    const float* ln_b    = (const float*)d_in[21];
    const float* W_a3    = (const float*)d_in[22];
    const float* b_a3    = (const float*)d_in[23];
    const int*   steps   = (const int*)d_in[24];
    float* out = (float*)d_out;

    cudaMemsetAsync(out, 0, (size_t)out_size * sizeof(float), 0);
    keys_kernel<<<1024, 256>>>((const float4*)W_k, b_k, (const float4*)enc);
    cudaFuncSetAttribute(seq_kernel, cudaFuncAttributeMaxDynamicSharedMemorySize, SMEM_BYTES);
    seq_kernel<<<CL, TPB, SMEM_BYTES>>>(out, steps, emask, ar, utype,
                                        W_fe, b_fe, W_a0, b_a0, W_a1, b_a1,
                                        W_f, b_f, W_i0, b_i0, W_i1, b_i1,
                                        W_o, b_o, ln_g, ln_b, W_a3, b_a3);
}

// round 3
// speedup vs baseline: 1.0801x; 1.0801x over previous
#include <cuda_runtime.h>
#include <cuda_bf16.h>
#include <cstdint>
#include <math.h>

#define FULLMASK 0xffffffffu
#define NENT   8192
#define EMB    256
#define KDIM   32
#define ARDIM  1024
#define UTYPE  233
#define CL     8
#define TPB    1024

// ---- smem layout (float offsets) ----
#define OFF_KEYS   0        // 32768
#define OFF_MASK   32768    // 8192 (replicated, updated identically)
#define OFF_W3T    40960    // 4096 = [32][128] transposed W_a3 slice
#define OFF_PART   45056    // 2048 = 8 ranks x 256 rows (everyone gets all partials)
#define OFF_WG     47104    // 8192 = 4 gates x 32 rows x 64
#define OFF_ARS    55296    // 128
#define OFF_C0     55424    // 256
#define OFF_A      55680    // 256
#define OFF_X      55936    // 64
#define OFF_Q      56000    // 32
#define OFF_H      56032    // 32
#define OFF_QN     56064    // 32
#define OFF_G      56096    // 128
#define OFF_CENT   56224    // 32
#define OFF_MB     56256    // 24: sums[8], maxv[8], maxi[8]
#define OFF_RED    56280    // 96: 32 warps x (sum,max,idx)
#define OFF_BIAS   56376    // 224: ba1,bf,bi0,bi1,bo,lng,lnb (32 each)
#define OFF_SCAL   56600    // 4: rowinv, pick, pending, done
#define SMEM_FLOATS 56604
#define SMEM_BYTES (SMEM_FLOATS * 4)

static __device__ float g_keys[KDIM * NENT];   // k-major: g_keys[k*NENT + e]

// ---------------- helpers ----------------
__device__ __forceinline__ uint32_t smem_u32(const void* p) {
    return (uint32_t)__cvta_generic_to_shared(p);
}
__device__ __forceinline__ uint32_t mapa_rank(uint32_t addr, uint32_t rank) {
    uint32_t r;
    asm volatile("mapa.shared::cluster.u32 %0, %1, %2;" : "=r"(r) : "r"(addr), "r"(rank));
    return r;
}
__device__ __forceinline__ void st_remote_f32(uint32_t addr, float v) {
    asm volatile("st.shared::cluster.f32 [%0], %1;" :: "r"(addr), "f"(v));
}
__device__ __forceinline__ void cluster_sync_all() {
    asm volatile("barrier.cluster.arrive.aligned;" ::: "memory");
    asm volatile("barrier.cluster.wait.aligned;" ::: "memory");
}
__device__ __forceinline__ uint32_t ctarank() {
    uint32_t r;
    asm("mov.u32 %0, %%cluster_ctarank;" : "=r"(r));
    return r;
}
__device__ __forceinline__ float wsum(float x) {
#pragma unroll
    for (int o = 16; o > 0; o >>= 1) x += __shfl_xor_sync(FULLMASK, x, o);
    return x;
}
__device__ __forceinline__ void argmax_red(float& v, float& idx) {
#pragma unroll
    for (int o = 16; o > 0; o >>= 1) {
        float ov = __shfl_xor_sync(FULLMASK, v, o);
        float oi = __shfl_xor_sync(FULLMASK, idx, o);
        if (ov > v || (ov == v && oi < idx)) { v = ov; idx = oi; }
    }
}
__device__ __forceinline__ float sigmoidf_(float x) { return 1.f / (1.f + expf(-x)); }
__device__ __forceinline__ float lnf(float x, float g, float b) {
    float m = wsum(x) * (1.f / 32.f);
    float d = x - m;
    float var = wsum(d * d) * (1.f / 32.f);
    return d * rsqrtf(var + 1e-5f) * g + b;
}

// ---------------- fused zero-fill + keys ----------------
__global__ void __launch_bounds__(256) zk_kernel(const float4* __restrict__ Wk,
                                                 const float* __restrict__ bk,
                                                 const float4* __restrict__ enc,
                                                 float4* __restrict__ out4,
                                                 int total4) {
    if (blockIdx.x < 1024) {
        int g = blockIdx.x * 256 + threadIdx.x;
        int e = g >> 5;
        int lane = g & 31;
        const float4* er = enc + (size_t)e * 64;
        const float4* wr = Wk + (size_t)lane * 64;
        float acc = 0.f;
#pragma unroll 8
        for (int j = 0; j < 64; j++) {
            float4 a = er[j];
            float4 b = wr[j];
            acc += a.x * b.x + a.y * b.y + a.z * b.z + a.w * b.w;
        }
        g_keys[lane * NENT + e] = acc + bk[lane];
    } else {
        const float4 z = make_float4(0.f, 0.f, 0.f, 0.f);
        int nz = (gridDim.x - 1024) * 256;
        for (int i = (blockIdx.x - 1024) * 256 + threadIdx.x; i < total4; i += nz)
            out4[i] = z;
    }
}

// ---------------- persistent sequential cluster kernel ----------------
__global__ void __cluster_dims__(CL, 1, 1) __launch_bounds__(TPB, 1)
seq_kernel(float* __restrict__ out,
           const int* __restrict__ p_steps,
           const float* __restrict__ entity_mask,
           const float* __restrict__ ar_in,
           const float* __restrict__ utype,
           const float* __restrict__ W_fe, const float* __restrict__ b_fe,
           const float* __restrict__ W_a0, const float* __restrict__ b_a0,
           const float* __restrict__ W_a1, const float* __restrict__ b_a1,
           const float* __restrict__ W_f,  const float* __restrict__ b_f,
           const float* __restrict__ W_i0, const float* __restrict__ b_i0,
           const float* __restrict__ W_i1, const float* __restrict__ b_i1,
           const float* __restrict__ W_o,  const float* __restrict__ b_o,
           const float* __restrict__ ln_g, const float* __restrict__ ln_b,
           const float* __restrict__ W_a3, const float* __restrict__ b_a3)
{
    extern __shared__ float sm[];
    const int tid  = threadIdx.x;
    const int lane = tid & 31;
    const int wid  = tid >> 5;
    const uint32_t rank = ctarank();
    const uint32_t smbase = smem_u32(sm);

    int raw = p_steps[0];
    int stepsv = (raw >= 0 && raw <= 100000) ? raw : (int)__int_as_float(raw);
    int steps = stepsv < 64 ? stepsv : 64;
    if (steps < 0) steps = 0;

    // ---- prologue (every CTA fully replicated small state) ----
#pragma unroll
    for (int k = 0; k < 32; k++)
        sm[OFF_KEYS + k * 1024 + tid] = g_keys[k * NENT + (int)rank * 1024 + tid];
#pragma unroll
    for (int i = 0; i < 8; i++)
        sm[OFF_MASK + i * 1024 + tid] = entity_mask[i * 1024 + tid];
#pragma unroll
    for (int i = 0; i < 4; i++) {
        int idx = tid + i * 1024;                     // idx = k*128 + t
        sm[OFF_W3T + idx] = W_a3[((int)rank * 128 + (idx & 127)) * 32 + (idx >> 7)];
    }
    {
        const float* gw[4] = { W_f, W_i0, W_i1, W_o };
#pragma unroll
        for (int g = 0; g < 4; g++) {
            sm[OFF_WG + g * 2048 + tid]        = gw[g][tid];
            sm[OFF_WG + g * 2048 + 1024 + tid] = gw[g][1024 + tid];
        }
    }
    float ba3 = 0.f;
    if (tid < 128) {
        sm[OFF_ARS + tid] = ar_in[(int)rank * 128 + tid];
        ba3 = b_a3[(int)rank * 128 + tid];
    }
    if (tid < 32) {
        sm[OFF_Q + tid] = 0.f; sm[OFF_H + tid] = 0.f;
        sm[OFF_BIAS +       tid] = b_a1[tid];
        sm[OFF_BIAS + 32  + tid] = b_f[tid];
        sm[OFF_BIAS + 64  + tid] = b_i0[tid];
        sm[OFF_BIAS + 96  + tid] = b_i1[tid];
        sm[OFF_BIAS + 128 + tid] = b_o[tid];
        sm[OFF_BIAS + 160 + tid] = ln_g[tid];
        sm[OFF_BIAS + 192 + tid] = ln_b[tid];
    }
    if (tid == 0) sm[OFF_SCAL + 3] = 0.f;   // done
    // C0 = b_a0 + relu(W_fe@utype + b_fe), replicated in every CTA
    for (int rr = 0; rr < 8; rr++) {
        int row = wid * 8 + rr;
        float acc = 0.f;
#pragma unroll
        for (int i = 0; i < 8; i++) {
            int j = lane + (i << 5);
            if (j < UTYPE) acc += W_fe[row * UTYPE + j] * utype[j];
        }
        acc = wsum(acc);
        if (lane == 0) sm[OFF_C0 + row] = b_a0[row] + fmaxf(0.f, acc + b_fe[row]);
    }
    // hoisted DSMEM destinations (lane -> destination rank)
    uint32_t part_dst = mapa_rank(smbase + (OFF_PART + (int)rank * 256) * 4u, (uint32_t)lane & 7u);
    uint32_t mb_dst   = mapa_rank(smbase + OFF_MB * 4u, (uint32_t)lane & 7u);
    cluster_sync_all();

    // ---- sequential steps: 2 cluster syncs per step ----
    for (int step = 0; step < steps; ++step) {
        __syncthreads();   // ARS/SCAL from prior step

        // S0: K-split GEMV partials, all-to-all scatter
        const float4* ars4 = (const float4*)(sm + OFF_ARS);
        float4 av = ars4[lane];
#pragma unroll
        for (int it = 0; it < 8; it++) {
            int row = it * 32 + wid;
            float4 w = ((const float4*)(W_a0 + (size_t)row * ARDIM + (int)rank * 128))[lane];
            float acc = w.x * av.x + w.y * av.y + w.z * av.z + w.w * av.w;
            acc = wsum(acc);
            if (lane < 8) st_remote_f32(part_dst + (uint32_t)row * 4u, acc);
        }
        cluster_sync_all();   // A: all partials everywhere

        // S1 (replicated): i0 sum -> relu -> i1 -> gates -> LSTM -> qn
        bool active = (sm[OFF_SCAL + 3] == 0.f);
        if (tid < 256) {
            float s = 0.f;
#pragma unroll
            for (int r = 0; r < 8; r++) s += sm[OFF_PART + r * 256 + tid];
            sm[OFF_A + tid] = fmaxf(0.f, s + sm[OFF_C0 + tid]);
        }
        __syncthreads();
        {   // i1 row per warp (W_a1 from L2)
            const float4* wr = (const float4*)(W_a1 + wid * EMB);
            const float4* a4 = (const float4*)(sm + OFF_A);
            float4 w0 = wr[lane * 2], w1 = wr[lane * 2 + 1];
            float4 x0 = a4[lane * 2], x1 = a4[lane * 2 + 1];
            float acc = w0.x * x0.x + w0.y * x0.y + w0.z * x0.z + w0.w * x0.w
                      + w1.x * x1.x + w1.y * x1.y + w1.z * x1.z + w1.w * x1.w;
            acc = wsum(acc);
            if (lane == 0) sm[OFF_X + wid] = fmaxf(0.f, acc + sm[OFF_BIAS + wid]);
        }
        if (wid == 1) sm[OFF_X + 32 + lane] = sm[OFF_Q + lane];
        __syncthreads();
        {   // 4 gate pre-activations from pinned smem weights
            float xl = sm[OFF_X + lane], xh = sm[OFF_X + 32 + lane];
            int b = wid * 64 + lane;
            float gf = sm[OFF_WG + b]        * xl + sm[OFF_WG + b + 32]        * xh;
            float g0 = sm[OFF_WG + 2048 + b] * xl + sm[OFF_WG + 2048 + b + 32] * xh;
            float g1 = sm[OFF_WG + 4096 + b] * xl + sm[OFF_WG + 4096 + b + 32] * xh;
            float go = sm[OFF_WG + 6144 + b] * xl + sm[OFF_WG + 6144 + b + 32] * xh;
            gf = wsum(gf); g0 = wsum(g0); g1 = wsum(g1); go = wsum(go);
            if (lane == 0) {
                sm[OFF_G +      wid] = gf + sm[OFF_BIAS + 32 + wid];
                sm[OFF_G + 32 + wid] = g0 + sm[OFF_BIAS + 64 + wid];
                sm[OFF_G + 64 + wid] = g1 + sm[OFF_BIAS + 96 + wid];
                sm[OFF_G + 96 + wid] = go + sm[OFF_BIAS + 128 + wid];
            }
        }
        __syncthreads();
        if (wid == 0) {
            float g = sm[OFF_BIAS + 160 + lane], b = sm[OFF_BIAS + 192 + lane];
            float gF = sm[OFF_G + lane], g0 = sm[OFF_G + 32 + lane];
            float g1 = sm[OFF_G + 64 + lane], gO = sm[OFF_G + 96 + lane];
            float forget = lnf(sigmoidf_(gF), g, b);
            float rem    = lnf(sigmoidf_(g0) * tanhf(g1), g, b);
            float hn     = rem + forget * sm[OFF_H + lane];
            float qn     = tanhf(hn) * lnf(sigmoidf_(gO), g, b);
            sm[OFF_QN + lane] = qn;
            if (active) { sm[OFF_Q + lane] = qn; sm[OFF_H + lane] = hn; }
        }
        __syncthreads();

        // S2: per-entity v + CTA reduce + all-to-all mailbox
        float a0 = 0.f, a1 = 0.f, a2 = 0.f, a3 = 0.f;
#pragma unroll
        for (int k = 0; k < 32; k += 4) {
            a0 += sm[OFF_QN + k]     * sm[OFF_KEYS + k * 1024 + tid];
            a1 += sm[OFF_QN + k + 1] * sm[OFF_KEYS + (k + 1) * 1024 + tid];
            a2 += sm[OFF_QN + k + 2] * sm[OFF_KEYS + (k + 2) * 1024 + tid];
            a3 += sm[OFF_QN + k + 3] * sm[OFF_KEYS + (k + 3) * 1024 + tid];
        }
        float dotv = (a0 + a1) + (a2 + a3);
        float sig = 1.f / (1.f + __expf(-dotv));
        float v = __expf(__logf(sig) * 1.25f);
        {
            float s = wsum(v);
            float mv = v, mi = (float)((int)rank * 1024 + tid);
            argmax_red(mv, mi);
            if (lane == 0) {
                sm[OFF_RED + wid * 3 + 0] = s;
                sm[OFF_RED + wid * 3 + 1] = mv;
                sm[OFF_RED + wid * 3 + 2] = mi;
            }
        }
        __syncthreads();
        if (wid == 0) {
            float s2 = sm[OFF_RED + lane * 3 + 0];
            float m2 = sm[OFF_RED + lane * 3 + 1];
            float i2 = sm[OFF_RED + lane * 3 + 2];
            s2 = wsum(s2); argmax_red(m2, i2);
            if (lane < 8) {
                st_remote_f32(mb_dst + ((uint32_t)rank) * 4u,        s2);
                st_remote_f32(mb_dst + (8u + (uint32_t)rank) * 4u,   m2);
                st_remote_f32(mb_dst + (16u + (uint32_t)rank) * 4u,  i2);
            }
        }
        cluster_sync_all();   // C: mailbox everywhere

        // S3 (replicated): global reduce, pick, selection, mask/flags update
        if (wid == 0) {
            float s  = (lane < 8) ? sm[OFF_MB + lane]      : 0.f;
            float m  = (lane < 8) ? sm[OFF_MB + 8 + lane]  : -INFINITY;
            float ix = (lane < 8) ? sm[OFF_MB + 16 + lane] : 1e9f;
            float ssum = wsum(s);
            argmax_red(m, ix);
            int pick = (int)ix;
            bool act2  = (sm[OFF_SCAL + 3] == 0.f);
            bool valid = (ssum != 0.f);
            float rowinv = (act2 && valid) ? 1.f / ssum : 0.f;
            float selv = g_keys[lane * NENT + pick];
            float mean = wsum(selv) * (1.f / 32.f);
            float cen = selv - mean;
            bool nanfree = (__ballot_sync(FULLMASK, isnan(cen)) == 0u);
            bool hit = act2 && valid && (sm[OFF_MASK + pick] != 0.f);
            bool pending = hit && nanfree;
            sm[OFF_CENT + lane] = cen;
            if (lane == 0) {
                sm[OFF_SCAL + 0] = rowinv;
                sm[OFF_SCAL + 1] = (float)pick;
                sm[OFF_SCAL + 2] = pending ? 1.f : 0.f;
                if (hit) {
                    sm[OFF_MASK + pick] = 0.f;
                    if (rank == 0) out[(size_t)NENT * NENT + pick] = 1.f;
                }
                if (hit && !nanfree) sm[OFF_SCAL + 3] = 1.f;
            }
        }
        __syncthreads();

        // S4 (local): row write + ar slice update
        out[(size_t)step * NENT + (int)rank * 1024 + tid] = v * sm[OFF_SCAL + 0];
        if (sm[OFF_SCAL + 2] != 0.f && tid < 128) {
            float d = 0.f;
#pragma unroll
            for (int k = 0; k < 32; k++) d += sm[OFF_W3T + k * 128 + tid] * sm[OFF_CENT + k];
            sm[OFF_ARS + tid] += fmaxf(0.f, d + ba3);
        }
    }

    __syncthreads();
    if (tid < 128)
        out[(size_t)NENT * NENT + NENT + (int)rank * 128 + tid] = sm[OFF_ARS + tid];
}

extern "C" void kernel_launch(void* const* d_in, const int* in_sizes, int n_in,
                              void* d_out, int out_size) {
    const float* utype   = (const float*)d_in[0];
    const float* emask   = (const float*)d_in[1];
    const float* enc     = (const float*)d_in[2];
    const float* ar      = (const float*)d_in[3];
    const float* W_fe    = (const float*)d_in[4];
    const float* b_fe    = (const float*)d_in[5];
    const float* W_k     = (const float*)d_in[6];
    const float* b_k     = (const float*)d_in[7];
    const float* W_a0    = (const float*)d_in[8];
    const float* b_a0    = (const float*)d_in[9];
    const float* W_a1    = (const float*)d_in[10];
    const float* b_a1    = (const float*)d_in[11];
    const float* W_f     = (const float*)d_in[12];
    const float* b_f     = (const float*)d_in[13];
    const float* W_i0    = (const float*)d_in[14];
    const float* b_i0    = (const float*)d_in[15];
    const float* W_i1    = (const float*)d_in[16];
    const float* b_i1    = (const float*)d_in[17];
    const float* W_o     = (const float*)d_in[18];
    const float* b_o     = (const float*)d_in[19];
    const float* ln_g    = (const float*)d_in[20];
    const float* ln_b    = (const float*)d_in[21];
    const float* W_a3    = (const float*)d_in[22];
    const float* b_a3    = (const float*)d_in[23];
    const int*   steps   = (const int*)d_in[24];
    float* out = (float*)d_out;

    int total4 = out_size / 4;   // out_size = 8192*8192 + 8192 + 1024, divisible by 4
    zk_kernel<<<1024 + 4096, 256>>>((const float4*)W_k, b_k, (const float4*)enc,
                                    (float4*)out, total4);
    cudaFuncSetAttribute(seq_kernel, cudaFuncAttributeMaxDynamicSharedMemorySize, SMEM_BYTES);
    seq_kernel<<<CL, TPB, SMEM_BYTES>>>(out, steps, emask, ar, utype,
                                        W_fe, b_fe, W_a0, b_a0, W_a1, b_a1,
                                        W_f, b_f, W_i0, b_i0, W_i1, b_i1,
                                        W_o, b_o, ln_g, ln_b, W_a3, b_a3);
}